// round 8
// baseline (speedup 1.0000x reference)
#include <cuda_runtime.h>
#include <cuda_fp16.h>
#include <cstdint>

#define F_DIM 128
#define MAX_NODES 100000
#define MAX_EDGES 3200000
#define KT 32
#define SPAD (KT + 4)

// Scratch (__device__ globals per harness rules)
__device__ float2 g_yh2[(size_t)MAX_NODES * (F_DIM / 4)]; // fp16 y (half2 pairs)
__device__ int    g_count[MAX_NODES + 1];
__device__ int    g_start[MAX_NODES + 1];
__device__ int    g_cursor[MAX_NODES];
__device__ int2   g_edges[MAX_EDGES];          // packed (col, val-as-int)

__device__ __forceinline__ uint32_t f32_to_tf32(float f) {
    uint32_t u;
    asm("cvt.rna.tf32.f32 %0, %1;" : "=r"(u) : "f"(f));
    return u;
}

// ---------------------------------------------------------------------------
// Kernel 1: y = x @ W^T -> fp16 via mma.sync tf32 tensor cores. (proven)
// ---------------------------------------------------------------------------
__global__ __launch_bounds__(256, 2)
void gemm_tf32_kernel(const float* __restrict__ x, const float* __restrict__ W,
                      int n_nodes) {
    __shared__ uint32_t As[128][SPAD];
    __shared__ uint32_t Ws[128][SPAD];

    const int tid  = threadIdx.x;
    const int warp = tid >> 5;
    const int lane = tid & 31;
    const int g    = lane >> 2;
    const int t    = lane & 3;
    const int m0   = blockIdx.x * 128;

    float c[16][4];
#pragma unroll
    for (int nt = 0; nt < 16; nt++)
#pragma unroll
        for (int i = 0; i < 4; i++) c[nt][i] = 0.0f;

    for (int kt = 0; kt < F_DIM; kt += KT) {
#pragma unroll
        for (int i = 0; i < 4; i++) {
            const int idx = tid + i * 256;
            const int r   = idx >> 3;
            const int cq  = (idx & 7) * 4;

            float4 av = make_float4(0.f, 0.f, 0.f, 0.f);
            if (m0 + r < n_nodes)
                av = *(const float4*)(x + (size_t)(m0 + r) * F_DIM + kt + cq);
            As[r][cq + 0] = f32_to_tf32(av.x);
            As[r][cq + 1] = f32_to_tf32(av.y);
            As[r][cq + 2] = f32_to_tf32(av.z);
            As[r][cq + 3] = f32_to_tf32(av.w);

            const float4 wv = *(const float4*)(W + (size_t)r * F_DIM + kt + cq);
            Ws[r][cq + 0] = f32_to_tf32(wv.x);
            Ws[r][cq + 1] = f32_to_tf32(wv.y);
            Ws[r][cq + 2] = f32_to_tf32(wv.z);
            Ws[r][cq + 3] = f32_to_tf32(wv.w);
        }
        __syncthreads();

#pragma unroll
        for (int ks = 0; ks < KT; ks += 8) {
            const uint32_t a0 = As[warp * 16 + g    ][ks + t];
            const uint32_t a1 = As[warp * 16 + g + 8][ks + t];
            const uint32_t a2 = As[warp * 16 + g    ][ks + t + 4];
            const uint32_t a3 = As[warp * 16 + g + 8][ks + t + 4];
#pragma unroll
            for (int nt = 0; nt < 16; nt++) {
                const uint32_t b0 = Ws[nt * 8 + g][ks + t];
                const uint32_t b1 = Ws[nt * 8 + g][ks + t + 4];
                asm volatile(
                    "mma.sync.aligned.m16n8k8.row.col.f32.tf32.tf32.f32 "
                    "{%0,%1,%2,%3}, {%4,%5,%6,%7}, {%8,%9}, {%0,%1,%2,%3};"
                    : "+f"(c[nt][0]), "+f"(c[nt][1]), "+f"(c[nt][2]), "+f"(c[nt][3])
                    : "r"(a0), "r"(a1), "r"(a2), "r"(a3), "r"(b0), "r"(b1));
            }
        }
        __syncthreads();
    }

    __half* yh = (__half*)g_yh2;
    const int r0 = m0 + warp * 16 + g;
    const int r1 = r0 + 8;
#pragma unroll
    for (int nt = 0; nt < 16; nt++) {
        const int col = nt * 8 + 2 * t;
        if (r0 < n_nodes)
            *(__half2*)(yh + (size_t)r0 * F_DIM + col) =
                __floats2half2_rn(c[nt][0], c[nt][1]);
        if (r1 < n_nodes)
            *(__half2*)(yh + (size_t)r1 * F_DIM + col) =
                __floats2half2_rn(c[nt][2], c[nt][3]);
    }
}

// ---------------------------------------------------------------------------
__global__ void zero_count_kernel(int n_nodes) {
    const int i = blockIdx.x * blockDim.x + threadIdx.x;
    if (i <= n_nodes) g_count[i] = 0;
}

// hist: 4 edges per thread (int4), streaming loads.
__global__ __launch_bounds__(256)
void hist_kernel(const int* __restrict__ rows, int n_edges) {
    const int base = (blockIdx.x * blockDim.x + threadIdx.x) * 4;
    if (base + 3 < n_edges) {
        const int4 r4 = __ldcs((const int4*)(rows + base));
        atomicAdd(&g_count[r4.x], 1);
        atomicAdd(&g_count[r4.y], 1);
        atomicAdd(&g_count[r4.z], 1);
        atomicAdd(&g_count[r4.w], 1);
    } else {
        for (int e = base; e < n_edges; e++)
            atomicAdd(&g_count[__ldcs(rows + e)], 1);
    }
}

// ---------------------------------------------------------------------------
// Fused exclusive scan: single block, 1024 threads, ~98 elems/thread.
// Writes g_start (exclusive prefix), g_cursor (copy), g_start[n] = total.
// ---------------------------------------------------------------------------
__global__ __launch_bounds__(1024)
void scan_fused_kernel(int n) {
    __shared__ int s[1024];
    const int t   = threadIdx.x;
    const int per = (n + 1023) / 1024;
    const int lo  = t * per;
    const int hi  = min(lo + per, n);

    int sum = 0;
    for (int i = lo; i < hi; i++) sum += g_count[i];
    s[t] = sum;
    __syncthreads();

    const int v = sum;
#pragma unroll
    for (int d = 1; d < 1024; d <<= 1) {
        int tt = (t >= d) ? s[t - d] : 0;
        __syncthreads();
        s[t] += tt;
        __syncthreads();
    }
    int prefix = s[t] - v;   // exclusive

    for (int i = lo; i < hi; i++) {
        g_start[i]  = prefix;
        g_cursor[i] = prefix;
        prefix += g_count[i];
    }
    if (t == 1023) g_start[n] = s[1023];
}

// reorder: 4 edges per thread, streaming loads/stores.
__global__ __launch_bounds__(256)
void reorder_kernel(const int* __restrict__ rows, const int* __restrict__ cols,
                    const float* __restrict__ vals, int n_edges) {
    const int base = (blockIdx.x * blockDim.x + threadIdx.x) * 4;
    if (base + 3 < n_edges) {
        const int4   r4 = __ldcs((const int4*)(rows + base));
        const int4   c4 = __ldcs((const int4*)(cols + base));
        const float4 v4 = __ldcs((const float4*)(vals + base));
        int pos;
        pos = atomicAdd(&g_cursor[r4.x], 1);
        __stcs(&g_edges[pos], make_int2(c4.x, __float_as_int(v4.x)));
        pos = atomicAdd(&g_cursor[r4.y], 1);
        __stcs(&g_edges[pos], make_int2(c4.y, __float_as_int(v4.y)));
        pos = atomicAdd(&g_cursor[r4.z], 1);
        __stcs(&g_edges[pos], make_int2(c4.z, __float_as_int(v4.z)));
        pos = atomicAdd(&g_cursor[r4.w], 1);
        __stcs(&g_edges[pos], make_int2(c4.w, __float_as_int(v4.w)));
    } else {
        for (int e = base; e < n_edges; e++) {
            const int pos = atomicAdd(&g_cursor[__ldcs(rows + e)], 1);
            __stcs(&g_edges[pos], make_int2(__ldcs(cols + e),
                                            __float_as_int(__ldcs(vals + e))));
        }
    }
}

// ---------------------------------------------------------------------------
// Accum: one warp per node. Half-warp split: lanes [0,16) process even edges,
// lanes [16,32) odd edges; lane handles 8 features (16B LDG.128 from y).
// ---------------------------------------------------------------------------
__global__ __launch_bounds__(256)
void accum_kernel(const float* __restrict__ b, float* __restrict__ out,
                  int n_nodes) {
    const int node = (blockIdx.x * blockDim.x + threadIdx.x) >> 5;
    if (node >= n_nodes) return;
    const int lane = threadIdx.x & 31;
    const int p    = lane & 15;   // feature group: [8p, 8p+8)
    const int h    = lane >> 4;   // edge parity

    const int s = g_start[node];
    const int e = g_start[node + 1];

    float acc[8];
#pragma unroll
    for (int i = 0; i < 8; i++) acc[i] = 0.0f;

    const __half* yh = (const __half*)g_yh2;

    for (int base = s; base < e; base += 32) {
        const int idx = base + lane;
        int2 ed = make_int2(0, 0);                 // col=0, val=0 -> no-op
        if (idx < e) ed = __ldcs(&g_edges[idx]);

#pragma unroll
        for (int jj = 0; jj < 16; jj++) {
            const int   src = 2 * jj + h;
            const int   col = __shfl_sync(0xffffffffu, ed.x, src);
            const float val = __int_as_float(__shfl_sync(0xffffffffu, ed.y, src));

            const uint4 raw = *(const uint4*)(yh + (size_t)col * F_DIM + p * 8);
            const __half2* hp = (const __half2*)&raw;
            const float2 f0 = __half22float2(hp[0]);
            const float2 f1 = __half22float2(hp[1]);
            const float2 f2 = __half22float2(hp[2]);
            const float2 f3 = __half22float2(hp[3]);
            acc[0] = fmaf(f0.x, val, acc[0]);
            acc[1] = fmaf(f0.y, val, acc[1]);
            acc[2] = fmaf(f1.x, val, acc[2]);
            acc[3] = fmaf(f1.y, val, acc[3]);
            acc[4] = fmaf(f2.x, val, acc[4]);
            acc[5] = fmaf(f2.y, val, acc[5]);
            acc[6] = fmaf(f3.x, val, acc[6]);
            acc[7] = fmaf(f3.y, val, acc[7]);
        }
    }

    // Combine the two halves (lane l and l^16 hold partial sums for same features).
#pragma unroll
    for (int i = 0; i < 8; i++)
        acc[i] += __shfl_xor_sync(0xffffffffu, acc[i], 16);

    // Lane writes features [8p + 4h, 8p + 4h + 4).
    const float4 bb = *(const float4*)(b + p * 8 + h * 4);
    __stcs((float4*)(out + (size_t)node * F_DIM + p * 8 + h * 4),
           make_float4(acc[h * 4 + 0] + bb.x, acc[h * 4 + 1] + bb.y,
                       acc[h * 4 + 2] + bb.z, acc[h * 4 + 3] + bb.w));
}

// ---------------------------------------------------------------------------
extern "C" void kernel_launch(void* const* d_in, const int* in_sizes, int n_in,
                              void* d_out, int out_size) {
    const int*   rows = (const int*)d_in[0];
    const int*   cols = (const int*)d_in[1];
    const float* vals = (const float*)d_in[2];
    const float* x    = (const float*)d_in[3];
    const float* W    = (const float*)d_in[4];
    const float* b    = (const float*)d_in[5];
    float*       out  = (float*)d_out;

    const int n_edges = in_sizes[0];
    const int n_nodes = in_sizes[3] / F_DIM;

    static cudaStream_t s2 = nullptr;
    static cudaEvent_t ev_fork = nullptr, ev_join = nullptr;
    if (s2 == nullptr) {
        cudaStreamCreateWithFlags(&s2, cudaStreamNonBlocking);
        cudaEventCreateWithFlags(&ev_fork, cudaEventDisableTiming);
        cudaEventCreateWithFlags(&ev_join, cudaEventDisableTiming);
    }

    // Fork: GEMM on the side stream (short branch).
    cudaEventRecord(ev_fork, 0);
    cudaStreamWaitEvent(s2, ev_fork, 0);

    gemm_tf32_kernel<<<(n_nodes + 127) / 128, 256, 0, s2>>>(x, W, n_nodes);

    // Main (critical): CSR build
    zero_count_kernel<<<(n_nodes + 256) / 256, 256>>>(n_nodes);
    {
        const int threads_needed = (n_edges + 3) / 4;
        hist_kernel<<<(threads_needed + 255) / 256, 256>>>(rows, n_edges);
    }
    scan_fused_kernel<<<1, 1024>>>(n_nodes);
    {
        const int threads_needed = (n_edges + 3) / 4;
        reorder_kernel<<<(threads_needed + 255) / 256, 256>>>(rows, cols, vals, n_edges);
    }

    // Join
    cudaEventRecord(ev_join, s2);
    cudaStreamWaitEvent(0, ev_join, 0);

    // Gather-accumulate, bias fused.
    accum_kernel<<<(n_nodes * 32 + 255) / 256, 256>>>(b, out, n_nodes);
}

// round 9
// speedup vs baseline: 1.7797x; 1.7797x over previous
#include <cuda_runtime.h>
#include <cuda_fp16.h>
#include <cstdint>

#define F_DIM 128
#define MAX_NODES 100000
#define MAX_EDGES 3200000
#define SCAN_BLK 1024
#define MAX_SCAN_BLOCKS ((MAX_NODES + SCAN_BLK - 1) / SCAN_BLK + 2)
#define KT 32
#define SPAD (KT + 4)

// Scratch (__device__ globals per harness rules)
__device__ float2 g_yh2[(size_t)MAX_NODES * (F_DIM / 4)]; // fp16 y (half2 pairs)
__device__ int    g_count[MAX_NODES + 1];
__device__ int    g_start[MAX_NODES + 1];
__device__ int    g_cursor[MAX_NODES];
__device__ int    g_blocksums[MAX_SCAN_BLOCKS];
__device__ int2   g_edges[MAX_EDGES];          // packed (col, val-as-int)

__device__ __forceinline__ uint32_t f32_to_tf32(float f) {
    uint32_t u;
    asm("cvt.rna.tf32.f32 %0, %1;" : "=r"(u) : "f"(f));
    return u;
}

// ---------------------------------------------------------------------------
// Kernel 1: y = x @ W^T -> fp16 via mma.sync tf32 tensor cores. (proven)
// ---------------------------------------------------------------------------
__global__ __launch_bounds__(256, 2)
void gemm_tf32_kernel(const float* __restrict__ x, const float* __restrict__ W,
                      int n_nodes) {
    __shared__ uint32_t As[128][SPAD];
    __shared__ uint32_t Ws[128][SPAD];

    const int tid  = threadIdx.x;
    const int warp = tid >> 5;
    const int lane = tid & 31;
    const int g    = lane >> 2;
    const int t    = lane & 3;
    const int m0   = blockIdx.x * 128;

    float c[16][4];
#pragma unroll
    for (int nt = 0; nt < 16; nt++)
#pragma unroll
        for (int i = 0; i < 4; i++) c[nt][i] = 0.0f;

    for (int kt = 0; kt < F_DIM; kt += KT) {
#pragma unroll
        for (int i = 0; i < 4; i++) {
            const int idx = tid + i * 256;
            const int r   = idx >> 3;
            const int cq  = (idx & 7) * 4;

            float4 av = make_float4(0.f, 0.f, 0.f, 0.f);
            if (m0 + r < n_nodes)
                av = *(const float4*)(x + (size_t)(m0 + r) * F_DIM + kt + cq);
            As[r][cq + 0] = f32_to_tf32(av.x);
            As[r][cq + 1] = f32_to_tf32(av.y);
            As[r][cq + 2] = f32_to_tf32(av.z);
            As[r][cq + 3] = f32_to_tf32(av.w);

            const float4 wv = *(const float4*)(W + (size_t)r * F_DIM + kt + cq);
            Ws[r][cq + 0] = f32_to_tf32(wv.x);
            Ws[r][cq + 1] = f32_to_tf32(wv.y);
            Ws[r][cq + 2] = f32_to_tf32(wv.z);
            Ws[r][cq + 3] = f32_to_tf32(wv.w);
        }
        __syncthreads();

#pragma unroll
        for (int ks = 0; ks < KT; ks += 8) {
            const uint32_t a0 = As[warp * 16 + g    ][ks + t];
            const uint32_t a1 = As[warp * 16 + g + 8][ks + t];
            const uint32_t a2 = As[warp * 16 + g    ][ks + t + 4];
            const uint32_t a3 = As[warp * 16 + g + 8][ks + t + 4];
#pragma unroll
            for (int nt = 0; nt < 16; nt++) {
                const uint32_t b0 = Ws[nt * 8 + g][ks + t];
                const uint32_t b1 = Ws[nt * 8 + g][ks + t + 4];
                asm volatile(
                    "mma.sync.aligned.m16n8k8.row.col.f32.tf32.tf32.f32 "
                    "{%0,%1,%2,%3}, {%4,%5,%6,%7}, {%8,%9}, {%0,%1,%2,%3};"
                    : "+f"(c[nt][0]), "+f"(c[nt][1]), "+f"(c[nt][2]), "+f"(c[nt][3])
                    : "r"(a0), "r"(a1), "r"(a2), "r"(a3), "r"(b0), "r"(b1));
            }
        }
        __syncthreads();
    }

    __half* yh = (__half*)g_yh2;
    const int r0 = m0 + warp * 16 + g;
    const int r1 = r0 + 8;
#pragma unroll
    for (int nt = 0; nt < 16; nt++) {
        const int col = nt * 8 + 2 * t;
        if (r0 < n_nodes)
            *(__half2*)(yh + (size_t)r0 * F_DIM + col) =
                __floats2half2_rn(c[nt][0], c[nt][1]);
        if (r1 < n_nodes)
            *(__half2*)(yh + (size_t)r1 * F_DIM + col) =
                __floats2half2_rn(c[nt][2], c[nt][3]);
    }
}

// ---------------------------------------------------------------------------
__global__ void zero_count_kernel(int n_nodes) {
    const int i = blockIdx.x * blockDim.x + threadIdx.x;
    if (i <= n_nodes) g_count[i] = 0;
}

// hist: 4 edges per thread (int4), streaming loads.
__global__ __launch_bounds__(256)
void hist_kernel(const int* __restrict__ rows, int n_edges) {
    const int base = (blockIdx.x * blockDim.x + threadIdx.x) * 4;
    if (base + 3 < n_edges) {
        const int4 r4 = __ldcs((const int4*)(rows + base));
        atomicAdd(&g_count[r4.x], 1);
        atomicAdd(&g_count[r4.y], 1);
        atomicAdd(&g_count[r4.z], 1);
        atomicAdd(&g_count[r4.w], 1);
    } else {
        for (int e = base; e < n_edges; e++)
            atomicAdd(&g_count[__ldcs(rows + e)], 1);
    }
}

// ---------------------------------------------------------------------------
// 3-kernel exclusive scan (proven ~6-7 us total on full chip).
// ---------------------------------------------------------------------------
__global__ __launch_bounds__(SCAN_BLK)
void scan1_kernel(int n) {
    __shared__ int s[SCAN_BLK];
    const int i = blockIdx.x * SCAN_BLK + threadIdx.x;
    const int v = (i < n) ? g_count[i] : 0;
    s[threadIdx.x] = v;
    __syncthreads();
#pragma unroll
    for (int d = 1; d < SCAN_BLK; d <<= 1) {
        int tt = (threadIdx.x >= d) ? s[threadIdx.x - d] : 0;
        __syncthreads();
        s[threadIdx.x] += tt;
        __syncthreads();
    }
    if (i < n) g_start[i] = s[threadIdx.x] - v;
    if (threadIdx.x == SCAN_BLK - 1) g_blocksums[blockIdx.x] = s[SCAN_BLK - 1];
}

__global__ void scan2_kernel(int nblocks, int n) {
    if (threadIdx.x == 0 && blockIdx.x == 0) {
        int acc = 0;
        for (int i = 0; i < nblocks; i++) {
            int t = g_blocksums[i];
            g_blocksums[i] = acc;
            acc += t;
        }
        g_start[n] = acc;
    }
}

__global__ __launch_bounds__(256)
void scan3_kernel(int n) {
    const int i = blockIdx.x * blockDim.x + threadIdx.x;
    if (i < n) {
        const int v = g_start[i] + g_blocksums[i >> 10];
        g_start[i]  = v;
        g_cursor[i] = v;
    }
}

// reorder: 4 edges per thread, streaming loads/stores.
__global__ __launch_bounds__(256)
void reorder_kernel(const int* __restrict__ rows, const int* __restrict__ cols,
                    const float* __restrict__ vals, int n_edges) {
    const int base = (blockIdx.x * blockDim.x + threadIdx.x) * 4;
    if (base + 3 < n_edges) {
        const int4   r4 = __ldcs((const int4*)(rows + base));
        const int4   c4 = __ldcs((const int4*)(cols + base));
        const float4 v4 = __ldcs((const float4*)(vals + base));
        int pos;
        pos = atomicAdd(&g_cursor[r4.x], 1);
        __stcs(&g_edges[pos], make_int2(c4.x, __float_as_int(v4.x)));
        pos = atomicAdd(&g_cursor[r4.y], 1);
        __stcs(&g_edges[pos], make_int2(c4.y, __float_as_int(v4.y)));
        pos = atomicAdd(&g_cursor[r4.z], 1);
        __stcs(&g_edges[pos], make_int2(c4.z, __float_as_int(v4.z)));
        pos = atomicAdd(&g_cursor[r4.w], 1);
        __stcs(&g_edges[pos], make_int2(c4.w, __float_as_int(v4.w)));
    } else {
        for (int e = base; e < n_edges; e++) {
            const int pos = atomicAdd(&g_cursor[__ldcs(rows + e)], 1);
            __stcs(&g_edges[pos], make_int2(__ldcs(cols + e),
                                            __float_as_int(__ldcs(vals + e))));
        }
    }
}

// ---------------------------------------------------------------------------
// Accum: one warp per node. Half-warp split: lanes [0,16) process even edges,
// lanes [16,32) odd edges; lane handles 8 features (16B LDG.128 from y).
// ---------------------------------------------------------------------------
__global__ __launch_bounds__(256)
void accum_kernel(const float* __restrict__ b, float* __restrict__ out,
                  int n_nodes) {
    const int node = (blockIdx.x * blockDim.x + threadIdx.x) >> 5;
    if (node >= n_nodes) return;
    const int lane = threadIdx.x & 31;
    const int p    = lane & 15;   // feature group: [8p, 8p+8)
    const int h    = lane >> 4;   // edge parity

    const int s = g_start[node];
    const int e = g_start[node + 1];

    float acc[8];
#pragma unroll
    for (int i = 0; i < 8; i++) acc[i] = 0.0f;

    const __half* yh = (const __half*)g_yh2;

    for (int base = s; base < e; base += 32) {
        const int idx = base + lane;
        int2 ed = make_int2(0, 0);                 // col=0, val=0 -> no-op
        if (idx < e) ed = __ldcs(&g_edges[idx]);

#pragma unroll
        for (int jj = 0; jj < 16; jj++) {
            const int   src = 2 * jj + h;
            const int   col = __shfl_sync(0xffffffffu, ed.x, src);
            const float val = __int_as_float(__shfl_sync(0xffffffffu, ed.y, src));

            const uint4 raw = *(const uint4*)(yh + (size_t)col * F_DIM + p * 8);
            const __half2* hp = (const __half2*)&raw;
            const float2 f0 = __half22float2(hp[0]);
            const float2 f1 = __half22float2(hp[1]);
            const float2 f2 = __half22float2(hp[2]);
            const float2 f3 = __half22float2(hp[3]);
            acc[0] = fmaf(f0.x, val, acc[0]);
            acc[1] = fmaf(f0.y, val, acc[1]);
            acc[2] = fmaf(f1.x, val, acc[2]);
            acc[3] = fmaf(f1.y, val, acc[3]);
            acc[4] = fmaf(f2.x, val, acc[4]);
            acc[5] = fmaf(f2.y, val, acc[5]);
            acc[6] = fmaf(f3.x, val, acc[6]);
            acc[7] = fmaf(f3.y, val, acc[7]);
        }
    }

    // Combine the two halves (lane l and l^16 hold partial sums for same features).
#pragma unroll
    for (int i = 0; i < 8; i++)
        acc[i] += __shfl_xor_sync(0xffffffffu, acc[i], 16);

    // Lane writes features [8p + 4h, 8p + 4h + 4).
    const float4 bb = *(const float4*)(b + p * 8 + h * 4);
    __stcs((float4*)(out + (size_t)node * F_DIM + p * 8 + h * 4),
           make_float4(acc[h * 4 + 0] + bb.x, acc[h * 4 + 1] + bb.y,
                       acc[h * 4 + 2] + bb.z, acc[h * 4 + 3] + bb.w));
}

// ---------------------------------------------------------------------------
extern "C" void kernel_launch(void* const* d_in, const int* in_sizes, int n_in,
                              void* d_out, int out_size) {
    const int*   rows = (const int*)d_in[0];
    const int*   cols = (const int*)d_in[1];
    const float* vals = (const float*)d_in[2];
    const float* x    = (const float*)d_in[3];
    const float* W    = (const float*)d_in[4];
    const float* b    = (const float*)d_in[5];
    float*       out  = (float*)d_out;

    const int n_edges = in_sizes[0];
    const int n_nodes = in_sizes[3] / F_DIM;
    const int nblocks_scan = (n_nodes + SCAN_BLK - 1) / SCAN_BLK;

    static cudaStream_t s2 = nullptr;
    static cudaEvent_t ev_fork = nullptr, ev_join = nullptr;
    if (s2 == nullptr) {
        cudaStreamCreateWithFlags(&s2, cudaStreamNonBlocking);
        cudaEventCreateWithFlags(&ev_fork, cudaEventDisableTiming);
        cudaEventCreateWithFlags(&ev_join, cudaEventDisableTiming);
    }

    // Fork: GEMM on the side stream (short branch).
    cudaEventRecord(ev_fork, 0);
    cudaStreamWaitEvent(s2, ev_fork, 0);

    gemm_tf32_kernel<<<(n_nodes + 127) / 128, 256, 0, s2>>>(x, W, n_nodes);

    // Main (critical): CSR build
    zero_count_kernel<<<(n_nodes + 256) / 256, 256>>>(n_nodes);
    {
        const int threads_needed = (n_edges + 3) / 4;
        hist_kernel<<<(threads_needed + 255) / 256, 256>>>(rows, n_edges);
    }
    scan1_kernel<<<nblocks_scan, SCAN_BLK>>>(n_nodes);
    scan2_kernel<<<1, 32>>>(nblocks_scan, n_nodes);
    scan3_kernel<<<(n_nodes + 255) / 256, 256>>>(n_nodes);
    {
        const int threads_needed = (n_edges + 3) / 4;
        reorder_kernel<<<(threads_needed + 255) / 256, 256>>>(rows, cols, vals, n_edges);
    }

    // Join
    cudaEventRecord(ev_join, s2);
    cudaStreamWaitEvent(0, ev_join, 0);

    // Gather-accumulate, bias fused.
    accum_kernel<<<(n_nodes * 32 + 255) / 256, 256>>>(b, out, n_nodes);
}